// round 15
// baseline (speedup 1.0000x reference)
#include <cuda_runtime.h>
#include <cuda_bf16.h>
#include <cstdint>

#define NTOK   4096       // B * S
#define DMODEL 1024
#define NHEAD  16
#define DKH    64
#define SEQ    2048
#define BATCH  2

// ---------------- scratch (__device__ globals; allocation-free rule) -------
__device__ __nv_bfloat16 g_Xhi[NTOK * DMODEL];
__device__ __nv_bfloat16 g_Xlo[NTOK * DMODEL];
__device__ __nv_bfloat16 g_Wthi[4][DMODEL * DMODEL];   // W^T [n][k], bf16 hi
__device__ __nv_bfloat16 g_Wtlo[4][DMODEL * DMODEL];   // W^T [n][k], bf16 lo
__device__ __nv_bfloat16 g_Qhi[NTOK * DMODEL];
__device__ __nv_bfloat16 g_Qlo[NTOK * DMODEL];
__device__ __nv_bfloat16 g_Khi[NTOK * DMODEL];
__device__ __nv_bfloat16 g_Klo[NTOK * DMODEL];
__device__ __nv_bfloat16 g_Vhi[NTOK * DMODEL];
__device__ __nv_bfloat16 g_Vlo[NTOK * DMODEL];
__device__ __nv_bfloat16 g_AOhi[NTOK * DMODEL];
__device__ __nv_bfloat16 g_AOlo[NTOK * DMODEL];

// ---------------- helpers ---------------------------------------------------
__device__ __forceinline__ uint32_t smem_to_u32(const void* p) {
    uint32_t a;
    asm("{ .reg .u64 t; cvta.to.shared.u64 t, %1; cvt.u32.u64 %0, t; }"
        : "=r"(a) : "l"(p));
    return a;
}
#define SMEM_SWIZZLE_128B(o) ((o) ^ (((o) >> 3) & 0x70))

#define CP_ASYNC16(dst, src) \
    asm volatile("cp.async.cg.shared.global [%0], [%1], 16;" \
        :: "r"(dst), "l"(src))
#define CP_COMMIT() asm volatile("cp.async.commit_group;" ::: "memory")
#define CP_WAIT(n)  asm volatile("cp.async.wait_group %0;" :: "n"(n) : "memory")

__device__ __forceinline__ void ldm_x4(uint32_t r[4], uint32_t addr) {
    asm volatile("ldmatrix.sync.aligned.m8n8.x4.shared.b16 {%0,%1,%2,%3}, [%4];"
                 : "=r"(r[0]), "=r"(r[1]), "=r"(r[2]), "=r"(r[3]) : "r"(addr));
}
__device__ __forceinline__ void ldm_x4_t(uint32_t r[4], uint32_t addr) {
    asm volatile("ldmatrix.sync.aligned.m8n8.x4.trans.shared.b16 {%0,%1,%2,%3}, [%4];"
                 : "=r"(r[0]), "=r"(r[1]), "=r"(r[2]), "=r"(r[3]) : "r"(addr));
}
__device__ __forceinline__ void mma_bf16(float c[4], const uint32_t a[4],
                                         uint32_t b0, uint32_t b1) {
    asm volatile(
        "mma.sync.aligned.m16n8k16.row.col.f32.bf16.bf16.f32 "
        "{%0,%1,%2,%3}, {%4,%5,%6,%7}, {%8,%9}, {%0,%1,%2,%3};"
        : "+f"(c[0]), "+f"(c[1]), "+f"(c[2]), "+f"(c[3])
        : "r"(a[0]), "r"(a[1]), "r"(a[2]), "r"(a[3]), "r"(b0), "r"(b1));
}
__device__ __forceinline__ uint32_t bf2(float a, float b) {
    __nv_bfloat162 t; t.x = __float2bfloat16(a); t.y = __float2bfloat16(b);
    return *(uint32_t*)&t;
}
__device__ __forceinline__ uint32_t bf2_hi_res(float a, float b, float& ra, float& rb) {
    __nv_bfloat16 ha = __float2bfloat16(a), hb = __float2bfloat16(b);
    ra = a - __bfloat162float(ha);
    rb = b - __bfloat162float(hb);
    __nv_bfloat162 t; t.x = ha; t.y = hb;
    return *(uint32_t*)&t;
}

// ---------------- conversion kernels ---------------------------------------
__global__ void conv_split_kernel(const float* __restrict__ xin)
{
    const int i = blockIdx.x * blockDim.x + threadIdx.x;   // one float4
    float4 v = ((const float4*)xin)[i];
    float r0, r1, r2, r3;
    uint32_t h01 = bf2_hi_res(v.x, v.y, r0, r1);
    uint32_t h23 = bf2_hi_res(v.z, v.w, r2, r3);
    ((uint32_t*)g_Xhi)[i * 2 + 0] = h01;
    ((uint32_t*)g_Xhi)[i * 2 + 1] = h23;
    ((uint32_t*)g_Xlo)[i * 2 + 0] = bf2(r0, r1);
    ((uint32_t*)g_Xlo)[i * 2 + 1] = bf2(r2, r3);
}

// transpose + split all 4 weights: Wt[n][k] = W[k][n]  (widx = blockIdx.z)
__global__ void conv_wt_kernel(const float* __restrict__ W0,
                               const float* __restrict__ W1,
                               const float* __restrict__ W2,
                               const float* __restrict__ W3)
{
    const int widx = blockIdx.z;
    const float* W = (widx == 0) ? W0 : (widx == 1) ? W1 : (widx == 2) ? W2 : W3;
    __shared__ float t[32][33];
    const int tx = threadIdx.x, ty = threadIdx.y;
    const int n0 = blockIdx.x * 32, k0 = blockIdx.y * 32;
#pragma unroll
    for (int i = ty; i < 32; i += 8)
        t[i][tx] = W[(size_t)(k0 + i) * DMODEL + n0 + tx];
    __syncthreads();
    __nv_bfloat16* hi = g_Wthi[widx];
    __nv_bfloat16* lo = g_Wtlo[widx];
#pragma unroll
    for (int i = ty; i < 32; i += 8) {
        float v = t[tx][i];                       // = W[k0+tx][n0+i]
        __nv_bfloat16 h = __float2bfloat16(v);
        size_t o = (size_t)(n0 + i) * DMODEL + k0 + tx;
        hi[o] = h;
        lo[o] = __float2bfloat16(v - __bfloat162float(h));
    }
}

// ---------------- bf16 mma.sync GEMM (unchanged from passing R13/R14) -------
// C = Ahi@Bhi + Ahi@Blo + Alo@Bhi + bias.  CTA 64x128, BK=64, 8 warps (2m x 4n),
// warp tile 32x32.  2-stage cp.async pipeline, 96KB smem -> 2 CTAs/SM.
#define GM_STAGE 49152
#define GM_SMEM  (2 * GM_STAGE)          // 98304 -> 2 CTAs/SM
#define GM_NCHUNK (DMODEL / 64)          // 16

__global__ __launch_bounds__(256, 2)
void gemm_tc_kernel(int qkvMode,
                    const float* __restrict__ bias0,
                    const float* __restrict__ bias1,
                    const float* __restrict__ bias2,
                    float* __restrict__ Cext)
{
    extern __shared__ __align__(1024) char smem[];
    const uint32_t smem_base = smem_to_u32(smem);
    const int tid  = threadIdx.x;
    const int lane = tid & 31;
    const int wid  = tid >> 5;
    const int warp_m = wid & 1;          // 0..1 -> 32-row group
    const int warp_n = wid >> 1;         // 0..3 -> 32-col group
    const int row0 = blockIdx.y * 64;
    const int col0 = blockIdx.x * 128;
    const int z = blockIdx.z;
    const int widx = qkvMode ? z : 3;

    const __nv_bfloat16* __restrict__ Ah = qkvMode ? g_Xhi : g_AOhi;
    const __nv_bfloat16* __restrict__ Al = qkvMode ? g_Xlo : g_AOlo;
    const __nv_bfloat16* __restrict__ Bh = g_Wthi[widx];
    const __nv_bfloat16* __restrict__ Bl = g_Wtlo[widx];
    const float* __restrict__ bias = (z == 0) ? bias0 : (z == 1) ? bias1 : bias2;

    float acc[2][4][4];
#pragma unroll
    for (int mt = 0; mt < 2; mt++)
#pragma unroll
        for (int nt = 0; nt < 4; nt++)
#pragma unroll
            for (int e = 0; e < 4; e++) acc[mt][nt][e] = 0.f;

    const int aRow   = lane & 15;
    const int aChunk = (lane >> 4) * 16;
    const int bRow   = (lane & 7) + ((lane >> 4) << 3);
    const int bChunk = ((lane >> 3) & 1) * 16;

    auto load_stage = [&](uint32_t sb, int k0) {
#pragma unroll
        for (int u = tid; u < 512; u += 256) {
            const int r = u >> 3, q = u & 7;
            const uint32_t so = SMEM_SWIZZLE_128B((uint32_t)(r * 128 + q * 16));
            const size_t ga = (size_t)(row0 + r) * DMODEL + k0 + q * 8;
            CP_ASYNC16(sb + so,        (const char*)(Ah + ga));
            CP_ASYNC16(sb + 8192 + so, (const char*)(Al + ga));
        }
#pragma unroll
        for (int u = tid; u < 1024; u += 256) {
            const int r = u >> 3, q = u & 7;
            const uint32_t so = SMEM_SWIZZLE_128B((uint32_t)(r * 128 + q * 16));
            const size_t gb = (size_t)(col0 + r) * DMODEL + k0 + q * 8;
            CP_ASYNC16(sb + 16384 + so, (const char*)(Bh + gb));
            CP_ASYNC16(sb + 32768 + so, (const char*)(Bl + gb));
        }
    };

    load_stage(smem_base, 0);
    CP_COMMIT();

    for (int chunk = 0; chunk < GM_NCHUNK; chunk++) {
        CP_WAIT(0);        // this stage's data landed
        __syncthreads();   // visible to all; other stage's readers done
        if (chunk + 1 < GM_NCHUNK) {
            load_stage(smem_base + ((chunk + 1) & 1) * GM_STAGE, (chunk + 1) * 64);
            CP_COMMIT();
        }
        const uint32_t sb = smem_base + (chunk & 1) * GM_STAGE;

#pragma unroll
        for (int ks = 0; ks < 4; ks++) {
            uint32_t ahf[2][4], alf[2][4];
            uint32_t bhf[2][4], blf[2][4];
#pragma unroll
            for (int mt = 0; mt < 2; mt++) {
                const uint32_t off = SMEM_SWIZZLE_128B(
                    (uint32_t)((warp_m * 32 + mt * 16 + aRow) * 128 + ks * 32 + aChunk));
                ldm_x4(ahf[mt], sb + off);
                ldm_x4(alf[mt], sb + 8192 + off);
            }
#pragma unroll
            for (int np = 0; np < 2; np++) {
                const uint32_t off = SMEM_SWIZZLE_128B(
                    (uint32_t)((warp_n * 32 + np * 16 + bRow) * 128 + ks * 32 + bChunk));
                ldm_x4(bhf[np], sb + 16384 + off);
                ldm_x4(blf[np], sb + 32768 + off);
            }
#pragma unroll
            for (int mt = 0; mt < 2; mt++)
#pragma unroll
                for (int nt = 0; nt < 4; nt++) {
                    const int np = nt >> 1, h = (nt & 1) * 2;
                    mma_bf16(acc[mt][nt], ahf[mt], bhf[np][h], bhf[np][h + 1]);
                    mma_bf16(acc[mt][nt], ahf[mt], blf[np][h], blf[np][h + 1]);
                    mma_bf16(acc[mt][nt], alf[mt], bhf[np][h], bhf[np][h + 1]);
                }
        }
    }

    const int erow = row0 + warp_m * 32 + (lane >> 2);
    const int ecol = col0 + warp_n * 32 + (lane & 3) * 2;
    if (qkvMode) {
        __nv_bfloat16* Chi = (z == 0) ? g_Qhi : (z == 1) ? g_Khi : g_Vhi;
        __nv_bfloat16* Clo = (z == 0) ? g_Qlo : (z == 1) ? g_Klo : g_Vlo;
#pragma unroll
        for (int mt = 0; mt < 2; mt++)
#pragma unroll
            for (int nt = 0; nt < 4; nt++) {
                const int row = erow + mt * 16;
                const int col = ecol + nt * 8;
                const float2 b2 = *(const float2*)&bias[col];
                float x0 = acc[mt][nt][0] + b2.x, x1 = acc[mt][nt][1] + b2.y;
                float x2 = acc[mt][nt][2] + b2.x, x3 = acc[mt][nt][3] + b2.y;
                float r0, r1, r2, r3;
                *(uint32_t*)&Chi[(size_t)row * DMODEL + col] = bf2_hi_res(x0, x1, r0, r1);
                *(uint32_t*)&Clo[(size_t)row * DMODEL + col] = bf2(r0, r1);
                *(uint32_t*)&Chi[(size_t)(row + 8) * DMODEL + col] = bf2_hi_res(x2, x3, r2, r3);
                *(uint32_t*)&Clo[(size_t)(row + 8) * DMODEL + col] = bf2(r2, r3);
            }
    } else {
#pragma unroll
        for (int mt = 0; mt < 2; mt++)
#pragma unroll
            for (int nt = 0; nt < 4; nt++) {
                const int row = erow + mt * 16;
                const int col = ecol + nt * 8;
                const float2 b2 = *(const float2*)&bias[col];
                *(float2*)&Cext[(size_t)row * DMODEL + col] =
                    make_float2(acc[mt][nt][0] + b2.x, acc[mt][nt][1] + b2.y);
                *(float2*)&Cext[(size_t)(row + 8) * DMODEL + col] =
                    make_float2(acc[mt][nt][2] + b2.x, acc[mt][nt][3] + b2.y);
            }
    }
}

// ---------------------------------------------------------------------------
// Tensor-core flash attention (Q/K roles swapped per reference):
//   out[i] = sum_{j<=i} softmax_j( K[i].Q[j] ) V[j]
// No running max (scores bounded; exp(s) fp32-safe; masked -> exp=0).
// Per-16-j-block fused S -> exp/pack -> PV pipeline: block b's exp/pack
// (MUFU/ALU) overlaps blocks b±1 mma/LDSM (tensor/L1). Accumulation order
// identical to the phase-separated version -> bit-identical results.
// K fragments in registers. 3-stage cp.async Q/V pipeline, occ 1.
// ---------------------------------------------------------------------------
#define AS_KHI 0
#define AS_KLO 16384
#define AS_ST0 32768            // stage: QHI 8K | QLO 8K | VHI 8K | VLO 8K
#define AS_STAGE 32768
#define AS_MADD (AS_ST0 + 3 * AS_STAGE)     // 3 x 64 floats
#define AS_TOTAL (AS_MADD + 768)            // 132 KB -> 1 CTA/SM

__global__ __launch_bounds__(256, 1)
void attn_tc_kernel(const int* __restrict__ amask)
{
    extern __shared__ __align__(1024) char smem[];
    const uint32_t sb = smem_to_u32(smem);
    float* maddS = (float*)(smem + AS_MADD);

    const int tid  = threadIdx.x;
    const int lane = tid & 31;
    const int wid  = tid >> 5;
    const int ib = (int)gridDim.x - 1 - (int)blockIdx.x;   // big blocks first
    const int h  = blockIdx.y;
    const int b  = blockIdx.z;
    const int tokBase = b * SEQ;
    const int i0 = ib * 128;
    const int dbase = h * DKH;

    const int aRow   = lane & 15;
    const int aChunk = (lane >> 4) * 16;
    const int bRow   = (lane & 7) + ((lane >> 4) << 3);
    const int bChunk = ((lane >> 3) & 1) * 16;
    const int vRow = (lane & 7) | (((lane >> 3) & 1) << 3);
    const int vCol = (lane >> 4) * 16;
    const int lc2 = (lane & 3) * 2;

    auto load_qv = [&](int st, int j0) {
        const uint32_t base = sb + AS_ST0 + st * AS_STAGE;
#pragma unroll
        for (int u = tid; u < 512; u += 256) {
            const int r = u >> 3, q = u & 7;
            const uint32_t so = SMEM_SWIZZLE_128B((uint32_t)(r * 128 + q * 16));
            const size_t g = (size_t)(tokBase + j0 + r) * DMODEL + dbase + q * 8;
            CP_ASYNC16(base + so,         (const char*)(g_Qhi + g));
            CP_ASYNC16(base + 8192 + so,  (const char*)(g_Qlo + g));
            CP_ASYNC16(base + 16384 + so, (const char*)(g_Vhi + g));
            CP_ASYNC16(base + 24576 + so, (const char*)(g_Vlo + g));
        }
        if (tid < 64)
            maddS[st * 64 + tid] =
                (amask[b * SEQ + j0 + tid] != 0) ? 0.f : -1e30f;
    };

    const int njb = 2 * ib + 2;   // always >= 2

    // prologue: group0 = K tile + stage0 Q/V;  group1 = stage1 Q/V
    for (int u = tid; u < 1024; u += 256) {
        const int r = u >> 3, q = u & 7;
        const uint32_t so = SMEM_SWIZZLE_128B((uint32_t)(r * 128 + q * 16));
        const size_t g = (size_t)(tokBase + i0 + r) * DMODEL + dbase + q * 8;
        CP_ASYNC16(sb + AS_KHI + so, (const char*)(g_Khi + g));
        CP_ASYNC16(sb + AS_KLO + so, (const char*)(g_Klo + g));
    }
    load_qv(0, 0);
    CP_COMMIT();
    load_qv(1, 64);
    CP_COMMIT();

    CP_WAIT(1);          // group0 (K + stage0) landed
    __syncthreads();

    // hoist K fragments to registers (loop-invariant)
    uint32_t kh[4][4], kl[4][4];
#pragma unroll
    for (int ks = 0; ks < 4; ks++) {
        const uint32_t aoff = SMEM_SWIZZLE_128B(
            (uint32_t)((wid * 16 + aRow) * 128 + ks * 32 + aChunk));
        ldm_x4(kh[ks], sb + AS_KHI + aoff);
        ldm_x4(kl[ks], sb + AS_KLO + aoff);
    }

    float o[8][4];
    float lA = 0.f, lB = 0.f;     // per-lane partial row sums (reduced at end)
#pragma unroll
    for (int t = 0; t < 8; t++)
#pragma unroll
        for (int e = 0; e < 4; e++) o[t][e] = 0.f;

    const int iA = i0 + wid * 16 + (lane >> 2);   // rows for c0,c1
    const int iB = iA + 8;                        // rows for c2,c3
    const int iwmax = i0 + wid * 16 + 15;

    int stage = 0;
    for (int jb = 0; jb < njb; jb++) {
        const int j0 = jb * 64;
        if (jb > 0) {
            if (jb + 1 < njb) { CP_WAIT(1); } else { CP_WAIT(0); }
            __syncthreads();
        }
        if (jb + 2 < njb) {
            int ns = stage + 2; if (ns >= 3) ns -= 3;
            load_qv(ns, j0 + 128);
            CP_COMMIT();
        }

        if (j0 <= iwmax) {
            const uint32_t qhb = sb + AS_ST0 + stage * AS_STAGE;
            const uint32_t qlb = qhb + 8192;
            const uint32_t vhb = qhb + 16384;
            const uint32_t vlb = qhb + 24576;
            const bool part = (j0 + 63 > i0 + wid * 16);
            const float* mrow = maddS + stage * 64;

            // ---- per-16-j-block fused S -> exp/pack -> PV ----
#pragma unroll
            for (int jblk = 0; jblk < 4; jblk++) {
                if (j0 + jblk * 16 > iwmax) break;   // fully-masked blocks: P==0

                // S(block) = K . Q^T (3-term split; K from registers)
                float s0[4], s1[4];
#pragma unroll
                for (int e = 0; e < 4; e++) { s0[e] = 0.f; s1[e] = 0.f; }
#pragma unroll
                for (int ks = 0; ks < 4; ks++) {
                    uint32_t qh[4], ql[4];
                    const uint32_t boff = SMEM_SWIZZLE_128B(
                        (uint32_t)((jblk * 16 + bRow) * 128 + ks * 32 + bChunk));
                    ldm_x4(qh, qhb + boff);
                    ldm_x4(ql, qlb + boff);
                    mma_bf16(s0, kh[ks], qh[0], qh[1]);
                    mma_bf16(s1, kh[ks], qh[2], qh[3]);
                    mma_bf16(s0, kh[ks], ql[0], ql[1]);
                    mma_bf16(s1, kh[ks], ql[2], ql[3]);
                    mma_bf16(s0, kl[ks], qh[0], qh[1]);
                    mma_bf16(s1, kl[ks], qh[2], qh[3]);
                }

                // mask + exp (no max subtraction; masked -> exp(-1e30)=0)
                const int t0 = jblk * 2, t1 = t0 + 1;
                {
                    const int jc0 = j0 + t0 * 8 + lc2;
                    const float m00 = mrow[t0 * 8 + lc2];
                    const float m01 = mrow[t0 * 8 + lc2 + 1];
                    float a0 = s0[0] + m00, a1 = s0[1] + m01;
                    float a2 = s0[2] + m00, a3 = s0[3] + m01;
                    if (part) {
                        if (jc0     > iA) a0 = -1e30f;
                        if (jc0 + 1 > iA) a1 = -1e30f;
                        if (jc0     > iB) a2 = -1e30f;
                        if (jc0 + 1 > iB) a3 = -1e30f;
                    }
                    s0[0] = __expf(a0); s0[1] = __expf(a1);
                    s0[2] = __expf(a2); s0[3] = __expf(a3);
                    lA += s0[0] + s0[1];
                    lB += s0[2] + s0[3];
                }
                {
                    const int jc1 = j0 + t1 * 8 + lc2;
                    const float m10 = mrow[t1 * 8 + lc2];
                    const float m11 = mrow[t1 * 8 + lc2 + 1];
                    float b0 = s1[0] + m10, b1 = s1[1] + m11;
                    float b2 = s1[2] + m10, b3 = s1[3] + m11;
                    if (part) {
                        if (jc1     > iA) b0 = -1e30f;
                        if (jc1 + 1 > iA) b1 = -1e30f;
                        if (jc1     > iB) b2 = -1e30f;
                        if (jc1 + 1 > iB) b3 = -1e30f;
                    }
                    s1[0] = __expf(b0); s1[1] = __expf(b1);
                    s1[2] = __expf(b2); s1[3] = __expf(b3);
                    lA += s1[0] + s1[1];
                    lB += s1[2] + s1[3];
                }

                // pack P (C-frag == A-frag layout) and PV(block)
                uint32_t ph[4], pl[4];
                float r0, r1;
                ph[0] = bf2_hi_res(s0[0], s0[1], r0, r1); pl[0] = bf2(r0, r1);
                ph[1] = bf2_hi_res(s0[2], s0[3], r0, r1); pl[1] = bf2(r0, r1);
                ph[2] = bf2_hi_res(s1[0], s1[1], r0, r1); pl[2] = bf2(r0, r1);
                ph[3] = bf2_hi_res(s1[2], s1[3], r0, r1); pl[3] = bf2(r0, r1);
#pragma unroll
                for (int np = 0; np < 4; np++) {
                    uint32_t vh[4], vl[4];
                    const uint32_t boff = SMEM_SWIZZLE_128B(
                        (uint32_t)((jblk * 16 + vRow) * 128 + np * 32 + vCol));
                    ldm_x4_t(vh, vhb + boff);
                    ldm_x4_t(vl, vlb + boff);
                    mma_bf16(o[np * 2],     ph, vh[0], vh[1]);
                    mma_bf16(o[np * 2 + 1], ph, vh[2], vh[3]);
                    mma_bf16(o[np * 2],     ph, vl[0], vl[1]);
                    mma_bf16(o[np * 2 + 1], ph, vl[2], vl[3]);
                    mma_bf16(o[np * 2],     pl, vh[0], vh[1]);
                    mma_bf16(o[np * 2 + 1], pl, vh[2], vh[3]);
                }
            }
        }
        if (++stage == 3) stage = 0;
    }

    // ---- epilogue: single cross-lane reduction of l, normalize, write ----
    lA += __shfl_xor_sync(0xffffffffu, lA, 1);
    lA += __shfl_xor_sync(0xffffffffu, lA, 2);
    lB += __shfl_xor_sync(0xffffffffu, lB, 1);
    lB += __shfl_xor_sync(0xffffffffu, lB, 2);
    const float ivA = 1.f / lA, ivB = 1.f / lB;
#pragma unroll
    for (int t = 0; t < 8; t++) {
        const int col = dbase + t * 8 + lc2;
        const size_t rA = (size_t)(tokBase + iA) * DMODEL + col;
        const size_t rB = (size_t)(tokBase + iB) * DMODEL + col;
        float r0, r1;
        *(uint32_t*)&g_AOhi[rA] = bf2_hi_res(o[t][0] * ivA, o[t][1] * ivA, r0, r1);
        *(uint32_t*)&g_AOlo[rA] = bf2(r0, r1);
        *(uint32_t*)&g_AOhi[rB] = bf2_hi_res(o[t][2] * ivB, o[t][3] * ivB, r0, r1);
        *(uint32_t*)&g_AOlo[rB] = bf2(r0, r1);
    }
}

// ---------------------------------------------------------------------------
extern "C" void kernel_launch(void* const* d_in, const int* in_sizes, int n_in,
                              void* d_out, int out_size)
{
    const float* x  = (const float*)d_in[0];
    const int*   am = (const int*)  d_in[1];
    const float* Wq = (const float*)d_in[2];
    const float* bq = (const float*)d_in[3];
    const float* Wk = (const float*)d_in[4];
    const float* bk = (const float*)d_in[5];
    const float* Wv = (const float*)d_in[6];
    const float* bv = (const float*)d_in[7];
    const float* Wo = (const float*)d_in[8];
    const float* bo = (const float*)d_in[9];
    float* out = (float*)d_out;

    conv_split_kernel<<<(NTOK * DMODEL / 4) / 256, 256>>>(x);
    const dim3 wtG(DMODEL / 32, DMODEL / 32, 4), wtB(32, 8);
    conv_wt_kernel<<<wtG, wtB>>>(Wq, Wk, Wv, Wo);

    cudaFuncSetAttribute(gemm_tc_kernel, cudaFuncAttributeMaxDynamicSharedMemorySize,
                         GM_SMEM);
    const dim3 gQKV(DMODEL / 128, NTOK / 64, 3);    // (8, 64, 3) = 1536 CTAs
    gemm_tc_kernel<<<gQKV, 256, GM_SMEM>>>(1, bq, bk, bv, nullptr);

    cudaFuncSetAttribute(attn_tc_kernel, cudaFuncAttributeMaxDynamicSharedMemorySize,
                         AS_TOTAL);
    const dim3 gAttn(SEQ / 128, NHEAD, BATCH);      // (16, 16, 2)
    attn_tc_kernel<<<gAttn, 256, AS_TOTAL>>>(am);

    const dim3 gO(DMODEL / 128, NTOK / 64, 1);      // (8, 64)
    gemm_tc_kernel<<<gO, 256, GM_SMEM>>>(0, bo, bo, bo, out);
}

// round 17
// speedup vs baseline: 1.0413x; 1.0413x over previous
#include <cuda_runtime.h>
#include <cuda_bf16.h>
#include <cstdint>

#define NTOK   4096       // B * S
#define DMODEL 1024
#define NHEAD  16
#define DKH    64
#define SEQ    2048
#define BATCH  2

// ---------------- scratch (__device__ globals; allocation-free rule) -------
__device__ __nv_bfloat16 g_Xhi[NTOK * DMODEL];
__device__ __nv_bfloat16 g_Xlo[NTOK * DMODEL];
__device__ __nv_bfloat16 g_Wthi[4][DMODEL * DMODEL];   // W^T [n][k], bf16 hi
__device__ __nv_bfloat16 g_Wtlo[4][DMODEL * DMODEL];   // W^T [n][k], bf16 lo
__device__ __nv_bfloat16 g_Qhi[NTOK * DMODEL];
__device__ __nv_bfloat16 g_Qlo[NTOK * DMODEL];
__device__ __nv_bfloat16 g_Khi[NTOK * DMODEL];
__device__ __nv_bfloat16 g_Klo[NTOK * DMODEL];
__device__ __nv_bfloat16 g_Vhi[NTOK * DMODEL];
__device__ __nv_bfloat16 g_Vlo[NTOK * DMODEL];
__device__ __nv_bfloat16 g_AOhi[NTOK * DMODEL];
__device__ __nv_bfloat16 g_AOlo[NTOK * DMODEL];

// ---------------- helpers ---------------------------------------------------
__device__ __forceinline__ uint32_t smem_to_u32(const void* p) {
    uint32_t a;
    asm("{ .reg .u64 t; cvta.to.shared.u64 t, %1; cvt.u32.u64 %0, t; }"
        : "=r"(a) : "l"(p));
    return a;
}
#define SMEM_SWIZZLE_128B(o) ((o) ^ (((o) >> 3) & 0x70))

#define CP_ASYNC16(dst, src) \
    asm volatile("cp.async.cg.shared.global [%0], [%1], 16;" \
        :: "r"(dst), "l"(src))
#define CP_COMMIT() asm volatile("cp.async.commit_group;" ::: "memory")
#define CP_WAIT(n)  asm volatile("cp.async.wait_group %0;" :: "n"(n) : "memory")

__device__ __forceinline__ void ldm_x4(uint32_t r[4], uint32_t addr) {
    asm volatile("ldmatrix.sync.aligned.m8n8.x4.shared.b16 {%0,%1,%2,%3}, [%4];"
                 : "=r"(r[0]), "=r"(r[1]), "=r"(r[2]), "=r"(r[3]) : "r"(addr));
}
__device__ __forceinline__ void ldm_x4_t(uint32_t r[4], uint32_t addr) {
    asm volatile("ldmatrix.sync.aligned.m8n8.x4.trans.shared.b16 {%0,%1,%2,%3}, [%4];"
                 : "=r"(r[0]), "=r"(r[1]), "=r"(r[2]), "=r"(r[3]) : "r"(addr));
}
__device__ __forceinline__ void mma_bf16(float c[4], const uint32_t a[4],
                                         uint32_t b0, uint32_t b1) {
    asm volatile(
        "mma.sync.aligned.m16n8k16.row.col.f32.bf16.bf16.f32 "
        "{%0,%1,%2,%3}, {%4,%5,%6,%7}, {%8,%9}, {%0,%1,%2,%3};"
        : "+f"(c[0]), "+f"(c[1]), "+f"(c[2]), "+f"(c[3])
        : "r"(a[0]), "r"(a[1]), "r"(a[2]), "r"(a[3]), "r"(b0), "r"(b1));
}
// pack {lo=a, hi=b} as bf16x2 in ONE cvt (round-nearest-even, == __float2bfloat16)
__device__ __forceinline__ uint32_t bf2(float a, float b) {
    uint32_t d;
    asm("cvt.rn.bf16x2.f32 %0, %1, %2;" : "=r"(d) : "f"(b), "f"(a));
    return d;
}
// pack hi pair + residuals via bf16<->f32 bit identity (bit-identical to old path)
__device__ __forceinline__ uint32_t bf2_hi_res(float a, float b, float& ra, float& rb) {
    const uint32_t d = bf2(a, b);
    ra = a - __uint_as_float(d << 16);            // f32(bf16_lo)
    rb = b - __uint_as_float(d & 0xffff0000u);    // f32(bf16_hi)
    return d;
}

// ---------------- conversion kernels ---------------------------------------
__global__ void conv_split_kernel(const float* __restrict__ xin)
{
    const int i = blockIdx.x * blockDim.x + threadIdx.x;   // one float4
    float4 v = ((const float4*)xin)[i];
    float r0, r1, r2, r3;
    uint32_t h01 = bf2_hi_res(v.x, v.y, r0, r1);
    uint32_t h23 = bf2_hi_res(v.z, v.w, r2, r3);
    ((uint32_t*)g_Xhi)[i * 2 + 0] = h01;
    ((uint32_t*)g_Xhi)[i * 2 + 1] = h23;
    ((uint32_t*)g_Xlo)[i * 2 + 0] = bf2(r0, r1);
    ((uint32_t*)g_Xlo)[i * 2 + 1] = bf2(r2, r3);
}

// transpose + split all 4 weights: Wt[n][k] = W[k][n]  (widx = blockIdx.z)
__global__ void conv_wt_kernel(const float* __restrict__ W0,
                               const float* __restrict__ W1,
                               const float* __restrict__ W2,
                               const float* __restrict__ W3)
{
    const int widx = blockIdx.z;
    const float* W = (widx == 0) ? W0 : (widx == 1) ? W1 : (widx == 2) ? W2 : W3;
    __shared__ float t[32][33];
    const int tx = threadIdx.x, ty = threadIdx.y;
    const int n0 = blockIdx.x * 32, k0 = blockIdx.y * 32;
#pragma unroll
    for (int i = ty; i < 32; i += 8)
        t[i][tx] = W[(size_t)(k0 + i) * DMODEL + n0 + tx];
    __syncthreads();
    __nv_bfloat16* hi = g_Wthi[widx];
    __nv_bfloat16* lo = g_Wtlo[widx];
#pragma unroll
    for (int i = ty; i < 32; i += 8) {
        float v = t[tx][i];                       // = W[k0+tx][n0+i]
        __nv_bfloat16 h = __float2bfloat16(v);
        size_t o = (size_t)(n0 + i) * DMODEL + k0 + tx;
        hi[o] = h;
        lo[o] = __float2bfloat16(v - __bfloat162float(h));
    }
}

// ---------------- bf16 mma.sync GEMM (unchanged from passing R13/R14) -------
// C = Ahi@Bhi + Ahi@Blo + Alo@Bhi + bias.  CTA 64x128, BK=64, 8 warps (2m x 4n),
// warp tile 32x32.  2-stage cp.async pipeline, 96KB smem -> 2 CTAs/SM.
#define GM_STAGE 49152
#define GM_SMEM  (2 * GM_STAGE)          // 98304 -> 2 CTAs/SM
#define GM_NCHUNK (DMODEL / 64)          // 16

__global__ __launch_bounds__(256, 2)
void gemm_tc_kernel(int qkvMode,
                    const float* __restrict__ bias0,
                    const float* __restrict__ bias1,
                    const float* __restrict__ bias2,
                    float* __restrict__ Cext)
{
    extern __shared__ __align__(1024) char smem[];
    const uint32_t smem_base = smem_to_u32(smem);
    const int tid  = threadIdx.x;
    const int lane = tid & 31;
    const int wid  = tid >> 5;
    const int warp_m = wid & 1;          // 0..1 -> 32-row group
    const int warp_n = wid >> 1;         // 0..3 -> 32-col group
    const int row0 = blockIdx.y * 64;
    const int col0 = blockIdx.x * 128;
    const int z = blockIdx.z;
    const int widx = qkvMode ? z : 3;

    const __nv_bfloat16* __restrict__ Ah = qkvMode ? g_Xhi : g_AOhi;
    const __nv_bfloat16* __restrict__ Al = qkvMode ? g_Xlo : g_AOlo;
    const __nv_bfloat16* __restrict__ Bh = g_Wthi[widx];
    const __nv_bfloat16* __restrict__ Bl = g_Wtlo[widx];
    const float* __restrict__ bias = (z == 0) ? bias0 : (z == 1) ? bias1 : bias2;

    float acc[2][4][4];
#pragma unroll
    for (int mt = 0; mt < 2; mt++)
#pragma unroll
        for (int nt = 0; nt < 4; nt++)
#pragma unroll
            for (int e = 0; e < 4; e++) acc[mt][nt][e] = 0.f;

    const int aRow   = lane & 15;
    const int aChunk = (lane >> 4) * 16;
    const int bRow   = (lane & 7) + ((lane >> 4) << 3);
    const int bChunk = ((lane >> 3) & 1) * 16;

    auto load_stage = [&](uint32_t sb, int k0) {
#pragma unroll
        for (int u = tid; u < 512; u += 256) {
            const int r = u >> 3, q = u & 7;
            const uint32_t so = SMEM_SWIZZLE_128B((uint32_t)(r * 128 + q * 16));
            const size_t ga = (size_t)(row0 + r) * DMODEL + k0 + q * 8;
            CP_ASYNC16(sb + so,        (const char*)(Ah + ga));
            CP_ASYNC16(sb + 8192 + so, (const char*)(Al + ga));
        }
#pragma unroll
        for (int u = tid; u < 1024; u += 256) {
            const int r = u >> 3, q = u & 7;
            const uint32_t so = SMEM_SWIZZLE_128B((uint32_t)(r * 128 + q * 16));
            const size_t gb = (size_t)(col0 + r) * DMODEL + k0 + q * 8;
            CP_ASYNC16(sb + 16384 + so, (const char*)(Bh + gb));
            CP_ASYNC16(sb + 32768 + so, (const char*)(Bl + gb));
        }
    };

    load_stage(smem_base, 0);
    CP_COMMIT();

    for (int chunk = 0; chunk < GM_NCHUNK; chunk++) {
        CP_WAIT(0);        // this stage's data landed
        __syncthreads();   // visible to all; other stage's readers done
        if (chunk + 1 < GM_NCHUNK) {
            load_stage(smem_base + ((chunk + 1) & 1) * GM_STAGE, (chunk + 1) * 64);
            CP_COMMIT();
        }
        const uint32_t sb = smem_base + (chunk & 1) * GM_STAGE;

#pragma unroll
        for (int ks = 0; ks < 4; ks++) {
            uint32_t ahf[2][4], alf[2][4];
            uint32_t bhf[2][4], blf[2][4];
#pragma unroll
            for (int mt = 0; mt < 2; mt++) {
                const uint32_t off = SMEM_SWIZZLE_128B(
                    (uint32_t)((warp_m * 32 + mt * 16 + aRow) * 128 + ks * 32 + aChunk));
                ldm_x4(ahf[mt], sb + off);
                ldm_x4(alf[mt], sb + 8192 + off);
            }
#pragma unroll
            for (int np = 0; np < 2; np++) {
                const uint32_t off = SMEM_SWIZZLE_128B(
                    (uint32_t)((warp_n * 32 + np * 16 + bRow) * 128 + ks * 32 + bChunk));
                ldm_x4(bhf[np], sb + 16384 + off);
                ldm_x4(blf[np], sb + 32768 + off);
            }
#pragma unroll
            for (int mt = 0; mt < 2; mt++)
#pragma unroll
                for (int nt = 0; nt < 4; nt++) {
                    const int np = nt >> 1, h = (nt & 1) * 2;
                    mma_bf16(acc[mt][nt], ahf[mt], bhf[np][h], bhf[np][h + 1]);
                    mma_bf16(acc[mt][nt], ahf[mt], blf[np][h], blf[np][h + 1]);
                    mma_bf16(acc[mt][nt], alf[mt], bhf[np][h], bhf[np][h + 1]);
                }
        }
    }

    const int erow = row0 + warp_m * 32 + (lane >> 2);
    const int ecol = col0 + warp_n * 32 + (lane & 3) * 2;
    if (qkvMode) {
        __nv_bfloat16* Chi = (z == 0) ? g_Qhi : (z == 1) ? g_Khi : g_Vhi;
        __nv_bfloat16* Clo = (z == 0) ? g_Qlo : (z == 1) ? g_Klo : g_Vlo;
#pragma unroll
        for (int mt = 0; mt < 2; mt++)
#pragma unroll
            for (int nt = 0; nt < 4; nt++) {
                const int row = erow + mt * 16;
                const int col = ecol + nt * 8;
                const float2 b2 = *(const float2*)&bias[col];
                float x0 = acc[mt][nt][0] + b2.x, x1 = acc[mt][nt][1] + b2.y;
                float x2 = acc[mt][nt][2] + b2.x, x3 = acc[mt][nt][3] + b2.y;
                float r0, r1, r2, r3;
                *(uint32_t*)&Chi[(size_t)row * DMODEL + col] = bf2_hi_res(x0, x1, r0, r1);
                *(uint32_t*)&Clo[(size_t)row * DMODEL + col] = bf2(r0, r1);
                *(uint32_t*)&Chi[(size_t)(row + 8) * DMODEL + col] = bf2_hi_res(x2, x3, r2, r3);
                *(uint32_t*)&Clo[(size_t)(row + 8) * DMODEL + col] = bf2(r2, r3);
            }
    } else {
#pragma unroll
        for (int mt = 0; mt < 2; mt++)
#pragma unroll
            for (int nt = 0; nt < 4; nt++) {
                const int row = erow + mt * 16;
                const int col = ecol + nt * 8;
                const float2 b2 = *(const float2*)&bias[col];
                *(float2*)&Cext[(size_t)row * DMODEL + col] =
                    make_float2(acc[mt][nt][0] + b2.x, acc[mt][nt][1] + b2.y);
                *(float2*)&Cext[(size_t)(row + 8) * DMODEL + col] =
                    make_float2(acc[mt][nt][2] + b2.x, acc[mt][nt][3] + b2.y);
            }
    }
}

// ---------------------------------------------------------------------------
// Tensor-core flash attention (Q/K roles swapped per reference) — R14 version:
//   out[i] = sum_{j<=i} softmax_j( K[i].Q[j] ) V[j]
// No running max (scores bounded; exp(s) fp32-safe; masked -> exp=0).
// Phase-separated per tile: [all S] -> [all exp] -> [all PV] (best measured).
// K fragments in registers. 3-stage cp.async Q/V pipeline, occ 1.
// ---------------------------------------------------------------------------
#define AS_KHI 0
#define AS_KLO 16384
#define AS_ST0 32768            // stage: QHI 8K | QLO 8K | VHI 8K | VLO 8K
#define AS_STAGE 32768
#define AS_MADD (AS_ST0 + 3 * AS_STAGE)     // 3 x 64 floats
#define AS_TOTAL (AS_MADD + 768)            // 132 KB -> 1 CTA/SM

__global__ __launch_bounds__(256, 1)
void attn_tc_kernel(const int* __restrict__ amask)
{
    extern __shared__ __align__(1024) char smem[];
    const uint32_t sb = smem_to_u32(smem);
    float* maddS = (float*)(smem + AS_MADD);

    const int tid  = threadIdx.x;
    const int lane = tid & 31;
    const int wid  = tid >> 5;
    const int ib = (int)gridDim.x - 1 - (int)blockIdx.x;   // big blocks first
    const int h  = blockIdx.y;
    const int b  = blockIdx.z;
    const int tokBase = b * SEQ;
    const int i0 = ib * 128;
    const int dbase = h * DKH;

    const int aRow   = lane & 15;
    const int aChunk = (lane >> 4) * 16;
    const int bRow   = (lane & 7) + ((lane >> 4) << 3);
    const int bChunk = ((lane >> 3) & 1) * 16;
    const int vRow = (lane & 7) | (((lane >> 3) & 1) << 3);
    const int vCol = (lane >> 4) * 16;

    auto load_qv = [&](int st, int j0) {
        const uint32_t base = sb + AS_ST0 + st * AS_STAGE;
#pragma unroll
        for (int u = tid; u < 512; u += 256) {
            const int r = u >> 3, q = u & 7;
            const uint32_t so = SMEM_SWIZZLE_128B((uint32_t)(r * 128 + q * 16));
            const size_t g = (size_t)(tokBase + j0 + r) * DMODEL + dbase + q * 8;
            CP_ASYNC16(base + so,         (const char*)(g_Qhi + g));
            CP_ASYNC16(base + 8192 + so,  (const char*)(g_Qlo + g));
            CP_ASYNC16(base + 16384 + so, (const char*)(g_Vhi + g));
            CP_ASYNC16(base + 24576 + so, (const char*)(g_Vlo + g));
        }
        if (tid < 64)
            maddS[st * 64 + tid] =
                (amask[b * SEQ + j0 + tid] != 0) ? 0.f : -1e30f;
    };

    const int njb = 2 * ib + 2;   // always >= 2

    // prologue: group0 = K tile + stage0 Q/V;  group1 = stage1 Q/V
    for (int u = tid; u < 1024; u += 256) {
        const int r = u >> 3, q = u & 7;
        const uint32_t so = SMEM_SWIZZLE_128B((uint32_t)(r * 128 + q * 16));
        const size_t g = (size_t)(tokBase + i0 + r) * DMODEL + dbase + q * 8;
        CP_ASYNC16(sb + AS_KHI + so, (const char*)(g_Khi + g));
        CP_ASYNC16(sb + AS_KLO + so, (const char*)(g_Klo + g));
    }
    load_qv(0, 0);
    CP_COMMIT();
    load_qv(1, 64);
    CP_COMMIT();

    CP_WAIT(1);          // group0 (K + stage0) landed
    __syncthreads();

    // hoist K fragments to registers (loop-invariant)
    uint32_t kh[4][4], kl[4][4];
#pragma unroll
    for (int ks = 0; ks < 4; ks++) {
        const uint32_t aoff = SMEM_SWIZZLE_128B(
            (uint32_t)((wid * 16 + aRow) * 128 + ks * 32 + aChunk));
        ldm_x4(kh[ks], sb + AS_KHI + aoff);
        ldm_x4(kl[ks], sb + AS_KLO + aoff);
    }

    float o[8][4];
    float lA = 0.f, lB = 0.f;     // per-lane partial row sums (reduced at end)
#pragma unroll
    for (int t = 0; t < 8; t++)
#pragma unroll
        for (int e = 0; e < 4; e++) o[t][e] = 0.f;

    const int iA = i0 + wid * 16 + (lane >> 2);   // rows for c0,c1
    const int iB = iA + 8;                        // rows for c2,c3
    const int iwmax = i0 + wid * 16 + 15;

    int stage = 0;
    for (int jb = 0; jb < njb; jb++) {
        const int j0 = jb * 64;
        if (jb > 0) {
            if (jb + 1 < njb) { CP_WAIT(1); } else { CP_WAIT(0); }
            __syncthreads();
        }
        if (jb + 2 < njb) {
            int ns = stage + 2; if (ns >= 3) ns -= 3;
            load_qv(ns, j0 + 128);
            CP_COMMIT();
        }

        if (j0 <= iwmax) {
            const uint32_t qhb = sb + AS_ST0 + stage * AS_STAGE;
            const uint32_t qlb = qhb + 8192;
            const uint32_t vhb = qhb + 16384;
            const uint32_t vlb = qhb + 24576;

            // ---- S = K . Q^T  (3-term split; K from registers) ----
            float s[8][4];
#pragma unroll
            for (int t = 0; t < 8; t++)
#pragma unroll
                for (int e = 0; e < 4; e++) s[t][e] = 0.f;

#pragma unroll
            for (int ks = 0; ks < 4; ks++) {
#pragma unroll
                for (int np = 0; np < 4; np++) {
                    uint32_t qh[4], ql[4];
                    const uint32_t boff = SMEM_SWIZZLE_128B(
                        (uint32_t)((np * 16 + bRow) * 128 + ks * 32 + bChunk));
                    ldm_x4(qh, qhb + boff);
                    ldm_x4(ql, qlb + boff);
                    mma_bf16(s[np * 2],     kh[ks], qh[0], qh[1]);
                    mma_bf16(s[np * 2 + 1], kh[ks], qh[2], qh[3]);
                    mma_bf16(s[np * 2],     kh[ks], ql[0], ql[1]);
                    mma_bf16(s[np * 2 + 1], kh[ks], ql[2], ql[3]);
                    mma_bf16(s[np * 2],     kl[ks], qh[0], qh[1]);
                    mma_bf16(s[np * 2 + 1], kl[ks], qh[2], qh[3]);
                }
            }

            // ---- mask + exp (no max subtraction; masked -> exp(-1e30)=0) ----
            const bool part = (j0 + 63 > i0 + wid * 16);
            const float* mrow = maddS + stage * 64;
#pragma unroll
            for (int t = 0; t < 8; t++) {
                const int jc = j0 + t * 8 + (lane & 3) * 2;
                const float m0 = mrow[t * 8 + (lane & 3) * 2];
                const float m1 = mrow[t * 8 + (lane & 3) * 2 + 1];
                float s0 = s[t][0] + m0, s1 = s[t][1] + m1;
                float s2 = s[t][2] + m0, s3 = s[t][3] + m1;
                if (part) {
                    if (jc     > iA) s0 = -1e30f;
                    if (jc + 1 > iA) s1 = -1e30f;
                    if (jc     > iB) s2 = -1e30f;
                    if (jc + 1 > iB) s3 = -1e30f;
                }
                s[t][0] = __expf(s0);
                s[t][1] = __expf(s1);
                s[t][2] = __expf(s2);
                s[t][3] = __expf(s3);
                lA += s[t][0] + s[t][1];
                lB += s[t][2] + s[t][3];
            }

            // ---- O += P.V  (P from registers; V via ldmatrix.trans) ----
#pragma unroll
            for (int ks = 0; ks < 4; ks++) {
                const int t0 = 2 * ks, t1 = t0 + 1;
                uint32_t ph[4], pl[4];
                float r0, r1;
                ph[0] = bf2_hi_res(s[t0][0], s[t0][1], r0, r1); pl[0] = bf2(r0, r1);
                ph[1] = bf2_hi_res(s[t0][2], s[t0][3], r0, r1); pl[1] = bf2(r0, r1);
                ph[2] = bf2_hi_res(s[t1][0], s[t1][1], r0, r1); pl[2] = bf2(r0, r1);
                ph[3] = bf2_hi_res(s[t1][2], s[t1][3], r0, r1); pl[3] = bf2(r0, r1);
#pragma unroll
                for (int np = 0; np < 4; np++) {
                    uint32_t vh[4], vl[4];
                    const uint32_t boff = SMEM_SWIZZLE_128B(
                        (uint32_t)((ks * 16 + vRow) * 128 + np * 32 + vCol));
                    ldm_x4_t(vh, vhb + boff);
                    ldm_x4_t(vl, vlb + boff);
                    mma_bf16(o[np * 2],     ph, vh[0], vh[1]);
                    mma_bf16(o[np * 2 + 1], ph, vh[2], vh[3]);
                    mma_bf16(o[np * 2],     ph, vl[0], vl[1]);
                    mma_bf16(o[np * 2 + 1], ph, vl[2], vl[3]);
                    mma_bf16(o[np * 2],     pl, vh[0], vh[1]);
                    mma_bf16(o[np * 2 + 1], pl, vh[2], vh[3]);
                }
            }
        }
        if (++stage == 3) stage = 0;
    }

    // ---- epilogue: single cross-lane reduction of l, normalize, write ----
    lA += __shfl_xor_sync(0xffffffffu, lA, 1);
    lA += __shfl_xor_sync(0xffffffffu, lA, 2);
    lB += __shfl_xor_sync(0xffffffffu, lB, 1);
    lB += __shfl_xor_sync(0xffffffffu, lB, 2);
    const float ivA = 1.f / lA, ivB = 1.f / lB;
#pragma unroll
    for (int t = 0; t < 8; t++) {
        const int col = dbase + t * 8 + (lane & 3) * 2;
        const size_t rA = (size_t)(tokBase + iA) * DMODEL + col;
        const size_t rB = (size_t)(tokBase + iB) * DMODEL + col;
        float r0, r1;
        *(uint32_t*)&g_AOhi[rA] = bf2_hi_res(o[t][0] * ivA, o[t][1] * ivA, r0, r1);
        *(uint32_t*)&g_AOlo[rA] = bf2(r0, r1);
        *(uint32_t*)&g_AOhi[rB] = bf2_hi_res(o[t][2] * ivB, o[t][3] * ivB, r0, r1);
        *(uint32_t*)&g_AOlo[rB] = bf2(r0, r1);
    }
}

// ---------------------------------------------------------------------------
extern "C" void kernel_launch(void* const* d_in, const int* in_sizes, int n_in,
                              void* d_out, int out_size)
{
    const float* x  = (const float*)d_in[0];
    const int*   am = (const int*)  d_in[1];
    const float* Wq = (const float*)d_in[2];
    const float* bq = (const float*)d_in[3];
    const float* Wk = (const float*)d_in[4];
    const float* bk = (const float*)d_in[5];
    const float* Wv = (const float*)d_in[6];
    const float* bv = (const float*)d_in[7];
    const float* Wo = (const float*)d_in[8];
    const float* bo = (const float*)d_in[9];
    float* out = (float*)d_out;

    conv_split_kernel<<<(NTOK * DMODEL / 4) / 256, 256>>>(x);
    const dim3 wtG(DMODEL / 32, DMODEL / 32, 4), wtB(32, 8);
    conv_wt_kernel<<<wtG, wtB>>>(Wq, Wk, Wv, Wo);

    cudaFuncSetAttribute(gemm_tc_kernel, cudaFuncAttributeMaxDynamicSharedMemorySize,
                         GM_SMEM);
    const dim3 gQKV(DMODEL / 128, NTOK / 64, 3);    // (8, 64, 3) = 1536 CTAs
    gemm_tc_kernel<<<gQKV, 256, GM_SMEM>>>(1, bq, bk, bv, nullptr);

    cudaFuncSetAttribute(attn_tc_kernel, cudaFuncAttributeMaxDynamicSharedMemorySize,
                         AS_TOTAL);
    const dim3 gAttn(SEQ / 128, NHEAD, BATCH);      // (16, 16, 2)
    attn_tc_kernel<<<gAttn, 256, AS_TOTAL>>>(am);

    const dim3 gO(DMODEL / 128, NTOK / 64, 1);      // (8, 64)
    gemm_tc_kernel<<<gO, 256, GM_SMEM>>>(0, bo, bo, bo, out);
}